// round 4
// baseline (speedup 1.0000x reference)
#include <cuda_runtime.h>

#define B 2
#define C 32
#define O 32
#define N 64
#define M 20
#define MM 400
#define MMM 8000
#define NN 4096

// Scratch (bss, allocation-free)
__device__ float g_Y2[(size_t)B * C * N * MM];   // fwd Y2 [bc][d][m]; reused as U1 [bo][d][m]
__device__ float g_Y3[(size_t)B * C * MMM];      // [bc][kd][m]
__device__ float g_Z [(size_t)B * O * MMM];      // [bo][kd][m]
__device__ float g_cf [N * M];                   // fwd table  [d][kd]
__device__ float g_ciT[M * N];                   // inv table  [kd][d]

// ---------------------------------------------------------------------------
// Compile-time DCT coefficients (Taylor cos, folded to FFMA immediates)
// ---------------------------------------------------------------------------
__host__ __device__ constexpr double tcos(int a) {      // cos(pi*a/128)
    double x = 3.14159265358979323846264338327950288 * (double)a / 128.0;
    double x2 = x * x, term = 1.0, s = 1.0;
    for (int i = 1; i <= 16; i++) { term *= -x2 / (double)((2 * i - 1) * (2 * i)); s += term; }
    return s;
}
__host__ __device__ constexpr int redu(int k, int n) {
    int a = (k * (2 * n + 1)) % 256;
    return (a > 128) ? 256 - a : a;
}
__host__ __device__ constexpr float CF(int n, int k) {  // forward DCT-II coeff
    double c = tcos(redu(k, n));
    return (k == 0) ? 1.0f : (float)(2.0 * c);
}
__host__ __device__ constexpr float CI(int n, int k) {  // inverse DCT-III coeff
    double c = tcos(redu(k, n));
    return (float)(((k == 0) ? 1.0 : c) / 64.0);
}

template<int I> struct ic { static constexpr int value = I; };
template<int I, int Nn> struct SF {
    template<class F> __device__ __forceinline__ static void run(F&& f) {
        f(ic<I>{}); SF<I + 1, Nn>::run(f);
    }
};
template<int Nn> struct SF<Nn, Nn> {
    template<class F> __device__ __forceinline__ static void run(F&&) {}
};
template<int Nn, class F> __device__ __forceinline__ void static_for(F&& f) { SF<0, Nn>::run(f); }

// ---------------------------------------------------------------------------
__global__ void init_mats_k() {
    int t = blockIdx.x * blockDim.x + threadIdx.x;
    if (t < N * M) {
        int n = t / M, k = t % M;
        g_cf[t] = CF(n, k);
        int k2 = t / N, n2 = t % N;
        g_ciT[t] = CI(n2, k2);
    }
}

// ---------------------------------------------------------------------------
// fwd_wh: x[slice][h][w] -> Y2[slice][kh][kw], 2 slices per block.
// Stage 1 reads x directly from gmem (no smem staging).
// ---------------------------------------------------------------------------
template<int KW0>
__device__ __forceinline__ void fwd_s1(const float* __restrict__ xr, float* __restrict__ tp) {
    float acc[10];
#pragma unroll
    for (int k = 0; k < 10; k++) acc[k] = 0.f;
    static_for<16>([&](auto W4) {
        constexpr int w4 = W4.value;
        float4 xv = *(const float4*)(xr + w4 * 4);
        static_for<10>([&](auto K) {
            constexpr int k = K.value;
            constexpr float c0 = CF(w4 * 4 + 0, KW0 + k);
            constexpr float c1 = CF(w4 * 4 + 1, KW0 + k);
            constexpr float c2 = CF(w4 * 4 + 2, KW0 + k);
            constexpr float c3 = CF(w4 * 4 + 3, KW0 + k);
            acc[k] += xv.x * c0; acc[k] += xv.y * c1;
            acc[k] += xv.z * c2; acc[k] += xv.w * c3;
        });
    });
#pragma unroll
    for (int k = 0; k < 10; k++) tp[KW0 + k] = acc[k];
}

template<int KH0>
__device__ __forceinline__ void fwd_s2(const float* __restrict__ tcol, float* __restrict__ outp, bool act) {
    float acc[5] = {0.f, 0.f, 0.f, 0.f, 0.f};
    static_for<64>([&](auto H) {
        constexpr int h = H.value;
        float tv = tcol[h * 21];
        static_for<5>([&](auto K) {
            constexpr int k = K.value;
            constexpr float c = CF(h, KH0 + k);
            acc[k] += tv * c;
        });
    });
    if (act) {
#pragma unroll
        for (int k = 0; k < 5; k++) outp[(KH0 + k) * 20] = acc[k];
    }
}

__global__ __launch_bounds__(256) void fwd_wh_k(const float* __restrict__ x) {
    __shared__ float tmp[2][64 * 21];
    int t = threadIdx.x, wid = t >> 5, lane = t & 31;
    int sl = wid >> 2, ws = wid & 3;
    int slice = blockIdx.x * 2 + sl;
    const float* xp = x + (size_t)slice * NN;
    {   // stage 1: tmp[h][kw] = sum_w x[h][w]*CF(w,kw)   (direct gmem reads)
        int h = (ws >> 1) * 32 + lane;
        const float* xr = xp + h * 64;
        float* tp = &tmp[sl][h * 21];
        if (ws & 1) fwd_s1<10>(xr, tp); else fwd_s1<0>(xr, tp);
    }
    __syncthreads();
    {   // stage 2: Y2[kh][kw] = sum_h CF(h,kh)*tmp[h][kw]
        bool act = lane < 20;
        int kwc = act ? lane : 0;
        const float* tcol = &tmp[sl][kwc];
        float* outp = g_Y2 + (size_t)slice * MM + kwc;
        switch (ws) {
            case 0: fwd_s2<0>(tcol, outp, act); break;
            case 1: fwd_s2<5>(tcol, outp, act); break;
            case 2: fwd_s2<10>(tcol, outp, act); break;
            default: fwd_s2<15>(tcol, outp, act); break;
        }
    }
}

// ---------------------------------------------------------------------------
// fwd_d: Y2[bc][d][m] -> Y3[bc][kd][m]   grid (64 bc, 4 mtile), block 128
// ---------------------------------------------------------------------------
__global__ __launch_bounds__(128) void fwd_d_k() {
    __shared__ float ys2[64 * 100];
    __shared__ float cfs[N * M];
    int bc = blockIdx.x, mt = blockIdx.y;
    int t = threadIdx.x, wid = t >> 5, lane = t & 31;
    const float* src = g_Y2 + (size_t)bc * (N * MM) + mt * 100;
    for (int i = t; i < 1600; i += 128) {
        int d = i / 25, j = (i % 25) * 4;
        *(float4*)&ys2[d * 100 + j] = *(const float4*)(src + (size_t)d * MM + j);
    }
    for (int i = t; i < N * M; i += 128) cfs[i] = g_cf[i];
    __syncthreads();
    int KD0 = wid * 5;                 // 4 warps x 5 kd
    bool act = lane < 25;
    int ml = act ? lane * 4 : 0;
    float4 acc[5];
#pragma unroll
    for (int k = 0; k < 5; k++) acc[k] = make_float4(0.f, 0.f, 0.f, 0.f);
#pragma unroll 4
    for (int d = 0; d < 64; d++) {
        float4 v = *(const float4*)&ys2[d * 100 + ml];
#pragma unroll
        for (int k = 0; k < 5; k++) {
            float cc = cfs[d * 20 + KD0 + k];
            acc[k].x += cc * v.x; acc[k].y += cc * v.y;
            acc[k].z += cc * v.z; acc[k].w += cc * v.w;
        }
    }
    if (act) {
        float* q = g_Y3 + (size_t)bc * MMM + mt * 100 + lane * 4;
#pragma unroll
        for (int k = 0; k < 5; k++) *(float4*)(q + (size_t)(KD0 + k) * MM) = acc[k];
    }
}

// ---------------------------------------------------------------------------
// mix: Z[b,o,m] = sum_c Y3[b,c,m]*W[c,o,m]
// grid (63 m-tiles of 128, 4 o-tiles of 8); warp = one o, lanes span m.
// ---------------------------------------------------------------------------
__global__ __launch_bounds__(256) void mix_k(const float* __restrict__ w) {
    __shared__ float ys[2 * C * 128];
    int mbase = blockIdx.x * 128, ot = blockIdx.y;
    int t = threadIdx.x;
    for (int i = t; i < 2048; i += 256) {           // 2048 float4 = 2*32*32
        int b = i >> 10, c = (i >> 5) & 31, m4 = i & 31;
        int m = mbase + m4 * 4;
        float4 v = make_float4(0.f, 0.f, 0.f, 0.f);
        if (m < MMM) v = *(const float4*)(g_Y3 + (size_t)(b * C + c) * MMM + m);
        *(float4*)&ys[(size_t)(b * C + c) * 128 + m4 * 4] = v;
    }
    __syncthreads();
    int wid = t >> 5, lane = t & 31;
    int o = ot * 8 + wid;
    int m0 = mbase + lane * 4;
    bool valid = m0 < MMM;
    float4 a0 = make_float4(0.f,0.f,0.f,0.f), a1 = a0;
    const float* y0b = &ys[lane * 4];
    const float* y1b = &ys[C * 128 + lane * 4];
#pragma unroll 8
    for (int c = 0; c < C; c++) {
        float4 wv = make_float4(0.f,0.f,0.f,0.f);
        if (valid) wv = *(const float4*)(w + ((size_t)c * O + o) * MMM + m0);
        float4 y0 = *(const float4*)(y0b + c * 128);
        float4 y1 = *(const float4*)(y1b + c * 128);
        a0.x += y0.x*wv.x; a0.y += y0.y*wv.y; a0.z += y0.z*wv.z; a0.w += y0.w*wv.w;
        a1.x += y1.x*wv.x; a1.y += y1.y*wv.y; a1.z += y1.z*wv.z; a1.w += y1.w*wv.w;
    }
    if (valid) {
        *(float4*)(g_Z + (size_t)o * MMM + m0) = a0;
        *(float4*)(g_Z + (size_t)(O + o) * MMM + m0) = a1;
    }
}

// ---------------------------------------------------------------------------
// inv_d: Z[bo][kd][m] -> U1[bo][d][m] (into g_Y2)  grid (64 bo, 4 dquarter)
// ---------------------------------------------------------------------------
__global__ __launch_bounds__(256) void inv_d_k() {
    __shared__ float zs[MMM];
    __shared__ float cis[M * N];      // [kd][d]
    int bo = blockIdx.x;
    int t = threadIdx.x, wid = t >> 5, lane = t & 31;
    const float* p = g_Z + (size_t)bo * MMM;
    for (int i = t; i < MMM / 4; i += 256)
        *(float4*)&zs[i * 4] = *(const float4*)(p + i * 4);
    for (int i = t; i < M * N; i += 256) cis[i] = g_ciT[i];
    __syncthreads();
    int mt = wid & 3;
    int d0 = blockIdx.y * 16 + (wid >> 2) * 8;
    bool act = lane < 25;
    int ml = act ? lane * 4 : 0;
    int m0 = mt * 100 + ml;
    float4 acc[8];
#pragma unroll
    for (int i = 0; i < 8; i++) acc[i] = make_float4(0.f,0.f,0.f,0.f);
#pragma unroll
    for (int kd = 0; kd < M; kd++) {
        float4 v = *(const float4*)&zs[kd * MM + m0];
        float4 c0 = *(const float4*)&cis[kd * N + d0];
        float4 c1 = *(const float4*)&cis[kd * N + d0 + 4];
        acc[0].x += c0.x*v.x; acc[0].y += c0.x*v.y; acc[0].z += c0.x*v.z; acc[0].w += c0.x*v.w;
        acc[1].x += c0.y*v.x; acc[1].y += c0.y*v.y; acc[1].z += c0.y*v.z; acc[1].w += c0.y*v.w;
        acc[2].x += c0.z*v.x; acc[2].y += c0.z*v.y; acc[2].z += c0.z*v.z; acc[2].w += c0.z*v.w;
        acc[3].x += c0.w*v.x; acc[3].y += c0.w*v.y; acc[3].z += c0.w*v.z; acc[3].w += c0.w*v.w;
        acc[4].x += c1.x*v.x; acc[4].y += c1.x*v.y; acc[4].z += c1.x*v.z; acc[4].w += c1.x*v.w;
        acc[5].x += c1.y*v.x; acc[5].y += c1.y*v.y; acc[5].z += c1.y*v.z; acc[5].w += c1.y*v.w;
        acc[6].x += c1.z*v.x; acc[6].y += c1.z*v.y; acc[6].z += c1.z*v.z; acc[6].w += c1.z*v.w;
        acc[7].x += c1.w*v.x; acc[7].y += c1.w*v.y; acc[7].z += c1.w*v.z; acc[7].w += c1.w*v.w;
    }
    if (act) {
        float* q = g_Y2 + (size_t)bo * (N * MM) + m0;
#pragma unroll
        for (int i = 0; i < 8; i++) *(float4*)(q + (size_t)(d0 + i) * MM) = acc[i];
    }
}

// ---------------------------------------------------------------------------
// inv_hw: U1[slice][kh][kw] -> out[slice][h][w], 2 slices per block.
// Stage 2 stores straight to gmem (64B contiguous per thread).
// ---------------------------------------------------------------------------
template<int HB>
__device__ __forceinline__ void inv_s1(const float* __restrict__ zcol, float* __restrict__ tcol, bool act) {
    float acc[16];
#pragma unroll
    for (int i = 0; i < 16; i++) acc[i] = 0.f;
    static_for<20>([&](auto KH) {
        constexpr int kh = KH.value;
        float zv = zcol[kh * 20];
        static_for<16>([&](auto I) {
            constexpr int i = I.value;
            constexpr float c = CI(HB + i, kh);
            acc[i] += zv * c;
        });
    });
    if (act) {
#pragma unroll
        for (int i = 0; i < 16; i++) tcol[(HB + i) * 21] = acc[i];
    }
}

template<int W0>
__device__ __forceinline__ void inv_s2(const float* __restrict__ trow, float* __restrict__ orow) {
    float acc[32];
#pragma unroll
    for (int i = 0; i < 32; i++) acc[i] = 0.f;
    static_for<20>([&](auto KW) {
        constexpr int kw = KW.value;
        float tv = trow[kw];
        static_for<32>([&](auto I) {
            constexpr int i = I.value;
            constexpr float c = CI(W0 + i, kw);
            acc[i] += tv * c;
        });
    });
#pragma unroll
    for (int i = 0; i < 8; i++) {
        float4 v = make_float4(acc[i*4], acc[i*4+1], acc[i*4+2], acc[i*4+3]);
        *(float4*)(orow + W0 + i * 4) = v;
    }
}

__global__ __launch_bounds__(256) void inv_hw_k(float* __restrict__ out) {
    __shared__ float zs[2][MM];
    __shared__ float tmp[2][64 * 21];
    int t = threadIdx.x, wid = t >> 5, lane = t & 31;
    int sl = wid >> 2, ws = wid & 3;
    int slice = blockIdx.x * 2 + sl;
    int t2 = t & 127;
    const float* p = g_Y2 + (size_t)slice * MM;
    for (int i = t2; i < MM; i += 128) zs[sl][i] = p[i];
    __syncthreads();
    {   // stage 1: tmp[h][kw] = sum_kh CI(h,kh)*zs[kh][kw]
        bool act = lane < 20;
        int kwc = act ? lane : 0;
        const float* zcol = &zs[sl][kwc];
        float* tcol = &tmp[sl][kwc];
        switch (ws) {
            case 0: inv_s1<0>(zcol, tcol, act); break;
            case 1: inv_s1<16>(zcol, tcol, act); break;
            case 2: inv_s1<32>(zcol, tcol, act); break;
            default: inv_s1<48>(zcol, tcol, act); break;
        }
    }
    __syncthreads();
    {   // stage 2: out[h][w] = sum_kw tmp[h][kw]*CI(w,kw)  (direct gmem stores)
        int h = (ws & 1) * 32 + lane;
        const float* trow = &tmp[sl][h * 21];
        float* orow = out + (size_t)slice * NN + h * 64;
        if (ws >> 1) inv_s2<32>(trow, orow); else inv_s2<0>(trow, orow);
    }
}

// ---------------------------------------------------------------------------
extern "C" void kernel_launch(void* const* d_in, const int* in_sizes, int n_in,
                              void* d_out, int out_size) {
    const float* x = (const float*)d_in[0];       // (2,32,64,64,64)
    const float* w = (const float*)d_in[1];       // (32,32,20,20,20)
    float* out = (float*)d_out;                   // (2,32,64,64,64)

    init_mats_k<<<5, 256>>>();
    fwd_wh_k<<<B * C * N / 2, 256>>>(x);          // 2048 blocks
    {
        dim3 g(B * C, 4);
        fwd_d_k<<<g, 128>>>();                    // 256 blocks
    }
    {
        dim3 g(63, 4);
        mix_k<<<g, 256>>>(w);                     // 252 blocks
    }
    {
        dim3 g(B * O, 4);
        inv_d_k<<<g, 256>>>();                    // 256 blocks
    }
    inv_hw_k<<<B * O * N / 2, 256>>>(out);        // 2048 blocks
}

// round 5
// speedup vs baseline: 1.2594x; 1.2594x over previous
#include <cuda_runtime.h>

#define B 2
#define C 32
#define O 32
#define N 64
#define M 20
#define MM 400
#define MMM 8000
#define NN 4096

// Scratch (bss, allocation-free)
__device__ float g_Y2[(size_t)B * C * N * MM];   // fwd Y2 [bc][d][m]; reused as U1 [bo][d][m]
__device__ float g_Y3[(size_t)B * C * MMM];      // [bc][kd][m]
__device__ float g_Z [(size_t)B * O * MMM];      // [bo][kd][m]
__device__ float g_cf [N * M];                   // fwd table  [d][kd]
__device__ float g_ciT[M * N];                   // inv table  [kd][d]

// ---------------------------------------------------------------------------
// Compile-time DCT coefficients (Taylor cos, folded to FFMA immediates)
// ---------------------------------------------------------------------------
__host__ __device__ constexpr double tcos(int a) {      // cos(pi*a/128)
    double x = 3.14159265358979323846264338327950288 * (double)a / 128.0;
    double x2 = x * x, term = 1.0, s = 1.0;
    for (int i = 1; i <= 16; i++) { term *= -x2 / (double)((2 * i - 1) * (2 * i)); s += term; }
    return s;
}
__host__ __device__ constexpr int redu(int k, int n) {
    int a = (k * (2 * n + 1)) % 256;
    return (a > 128) ? 256 - a : a;
}
__host__ __device__ constexpr float CF(int n, int k) {  // forward DCT-II coeff
    double c = tcos(redu(k, n));
    return (k == 0) ? 1.0f : (float)(2.0 * c);
}
__host__ __device__ constexpr float CI(int n, int k) {  // inverse DCT-III coeff
    double c = tcos(redu(k, n));
    return (float)(((k == 0) ? 1.0 : c) / 64.0);
}

template<int I> struct ic { static constexpr int value = I; };
template<int I, int Nn> struct SF {
    template<class F> __device__ __forceinline__ static void run(F&& f) {
        f(ic<I>{}); SF<I + 1, Nn>::run(f);
    }
};
template<int Nn> struct SF<Nn, Nn> {
    template<class F> __device__ __forceinline__ static void run(F&&) {}
};
template<int Nn, class F> __device__ __forceinline__ void static_for(F&& f) { SF<0, Nn>::run(f); }

// ---------------------------------------------------------------------------
__global__ void init_mats_k() {
    int t = blockIdx.x * blockDim.x + threadIdx.x;
    if (t < N * M) {
        int n = t / M, k = t % M;
        g_cf[t] = CF(n, k);
        int k2 = t / N, n2 = t % N;
        g_ciT[t] = CI(n2, k2);
    }
}

// ---------------------------------------------------------------------------
// fwd_wh: x[slice][h][w] -> Y2[slice][kh][kw], 2 slices per block.
// Stage 1/2 use cosine butterfly: CF(63-n,k) = (-1)^k CF(n,k).
// ---------------------------------------------------------------------------
template<int KW0>
__device__ __forceinline__ void fwd_s1(const float* __restrict__ xr, float* __restrict__ tp) {
    float acc[10];
#pragma unroll
    for (int k = 0; k < 10; k++) acc[k] = 0.f;
    static_for<32>([&](auto W) {
        constexpr int w = W.value;
        float a = xr[w], b = xr[63 - w];
        float s = a + b, d = a - b;
        static_for<10>([&](auto K) {
            constexpr int k = K.value;
            constexpr int kw = KW0 + k;
            constexpr float c = CF(w, kw);
            acc[k] += ((kw & 1) ? d : s) * c;
        });
    });
#pragma unroll
    for (int k = 0; k < 10; k++) tp[KW0 + k] = acc[k];
}

template<int KH0>
__device__ __forceinline__ void fwd_s2(const float* __restrict__ tcol, float* __restrict__ outp, bool act) {
    float acc[5] = {0.f, 0.f, 0.f, 0.f, 0.f};
    static_for<32>([&](auto H) {
        constexpr int h = H.value;
        float a = tcol[h * 21], b = tcol[(63 - h) * 21];
        float s = a + b, d = a - b;
        static_for<5>([&](auto K) {
            constexpr int k = K.value;
            constexpr int kh = KH0 + k;
            constexpr float c = CF(h, kh);
            acc[k] += ((kh & 1) ? d : s) * c;
        });
    });
    if (act) {
#pragma unroll
        for (int k = 0; k < 5; k++) outp[(KH0 + k) * 20] = acc[k];
    }
}

__global__ __launch_bounds__(256) void fwd_wh_k(const float* __restrict__ x) {
    __shared__ float xs[2][64 * 65];      // [h][w], pad 65 (conflict-free scalar LDS)
    __shared__ float tmp[2][64 * 21];
    int t = threadIdx.x, wid = t >> 5, lane = t & 31;
    int sl = wid >> 2, ws = wid & 3;
    int slice = blockIdx.x * 2 + sl;
    const float* xp = x + (size_t)slice * NN;
    int t2 = t & 127;
#pragma unroll
    for (int r = 0; r < 8; r++) {
        int idx = t2 + r * 128;           // float4 index 0..1023
        int h = idx >> 4, w4 = idx & 15;
        float4 v = *(const float4*)(xp + idx * 4);
        float* dst = &xs[sl][h * 65 + w4 * 4];
        dst[0] = v.x; dst[1] = v.y; dst[2] = v.z; dst[3] = v.w;
    }
    __syncthreads();
    {   // stage 1: tmp[h][kw] = sum_w xs[h][w]*CF(w,kw)   (butterfly)
        int h = (ws >> 1) * 32 + lane;
        const float* xr = &xs[sl][h * 65];
        float* tp = &tmp[sl][h * 21];
        if (ws & 1) fwd_s1<10>(xr, tp); else fwd_s1<0>(xr, tp);
    }
    __syncthreads();
    {   // stage 2: Y2[kh][kw] = sum_h CF(h,kh)*tmp[h][kw]   (butterfly)
        bool act = lane < 20;
        int kwc = act ? lane : 0;
        const float* tcol = &tmp[sl][kwc];
        float* outp = g_Y2 + (size_t)slice * MM + kwc;
        switch (ws) {
            case 0: fwd_s2<0>(tcol, outp, act); break;
            case 1: fwd_s2<5>(tcol, outp, act); break;
            case 2: fwd_s2<10>(tcol, outp, act); break;
            default: fwd_s2<15>(tcol, outp, act); break;
        }
    }
}

// ---------------------------------------------------------------------------
// fwd_d: Y2[bc][d][m] -> Y3[bc][kd][m]   grid (64 bc, 4 mtile), block 128
// ---------------------------------------------------------------------------
__global__ __launch_bounds__(128) void fwd_d_k() {
    __shared__ float ys2[64 * 100];
    __shared__ float cfs[N * M];
    int bc = blockIdx.x, mt = blockIdx.y;
    int t = threadIdx.x, wid = t >> 5, lane = t & 31;
    const float* src = g_Y2 + (size_t)bc * (N * MM) + mt * 100;
    for (int i = t; i < 1600; i += 128) {
        int d = i / 25, j = (i % 25) * 4;
        *(float4*)&ys2[d * 100 + j] = *(const float4*)(src + (size_t)d * MM + j);
    }
    for (int i = t; i < N * M; i += 128) cfs[i] = g_cf[i];
    __syncthreads();
    int KD0 = wid * 5;
    bool act = lane < 25;
    int ml = act ? lane * 4 : 0;
    float4 acc[5];
#pragma unroll
    for (int k = 0; k < 5; k++) acc[k] = make_float4(0.f, 0.f, 0.f, 0.f);
#pragma unroll 4
    for (int d = 0; d < 64; d++) {
        float4 v = *(const float4*)&ys2[d * 100 + ml];
#pragma unroll
        for (int k = 0; k < 5; k++) {
            float cc = cfs[d * 20 + KD0 + k];
            acc[k].x += cc * v.x; acc[k].y += cc * v.y;
            acc[k].z += cc * v.z; acc[k].w += cc * v.w;
        }
    }
    if (act) {
        float* q = g_Y3 + (size_t)bc * MMM + mt * 100 + lane * 4;
#pragma unroll
        for (int k = 0; k < 5; k++) *(float4*)(q + (size_t)(KD0 + k) * MM) = acc[k];
    }
}

// ---------------------------------------------------------------------------
// mix: Z[b,o,m] = sum_c Y3[b,c,m]*W[c,o,m]
// grid (63 m-tiles of 128, 4 o-tiles of 8); warp = one o, lanes span m.
// Weight loads explicitly batched 16-deep for MLP.
// ---------------------------------------------------------------------------
__global__ __launch_bounds__(256) void mix_k(const float* __restrict__ w) {
    __shared__ float ys[2 * C * 128];
    int mbase = blockIdx.x * 128, ot = blockIdx.y;
    int t = threadIdx.x;
    for (int i = t; i < 2048; i += 256) {           // 2048 float4
        int b = i >> 10, c = (i >> 5) & 31, m4 = i & 31;
        int m = mbase + m4 * 4;
        float4 v = make_float4(0.f, 0.f, 0.f, 0.f);
        if (m < MMM) v = *(const float4*)(g_Y3 + (size_t)(b * C + c) * MMM + m);
        *(float4*)&ys[(size_t)(b * C + c) * 128 + m4 * 4] = v;
    }
    __syncthreads();
    int wid = t >> 5, lane = t & 31;
    int o = ot * 8 + wid;
    int m0 = mbase + lane * 4;
    bool valid = m0 < MMM;
    const float* wp = w + (size_t)o * MMM + (valid ? m0 : 0);
    float4 a0 = make_float4(0.f,0.f,0.f,0.f), a1 = a0;
#pragma unroll
    for (int cc = 0; cc < 32; cc += 16) {
        float4 wr[16];
#pragma unroll
        for (int j = 0; j < 16; j++)
            wr[j] = *(const float4*)(wp + (size_t)(cc + j) * (O * MMM));
#pragma unroll
        for (int j = 0; j < 16; j++) {
            int c = cc + j;
            float4 y0 = *(const float4*)&ys[c * 128 + lane * 4];
            float4 y1 = *(const float4*)&ys[(C + c) * 128 + lane * 4];
            a0.x += y0.x*wr[j].x; a0.y += y0.y*wr[j].y; a0.z += y0.z*wr[j].z; a0.w += y0.w*wr[j].w;
            a1.x += y1.x*wr[j].x; a1.y += y1.y*wr[j].y; a1.z += y1.z*wr[j].z; a1.w += y1.w*wr[j].w;
        }
    }
    if (valid) {
        *(float4*)(g_Z + (size_t)o * MMM + m0) = a0;
        *(float4*)(g_Z + (size_t)(O + o) * MMM + m0) = a1;
    }
}

// ---------------------------------------------------------------------------
// inv_d: Z[bo][kd][m] -> U1[bo][d][m] (into g_Y2)  grid (64 bo, 4 dquarter)
// ---------------------------------------------------------------------------
__global__ __launch_bounds__(256) void inv_d_k() {
    __shared__ float zs[MMM];
    __shared__ float cis[M * N];      // [kd][d]
    int bo = blockIdx.x;
    int t = threadIdx.x, wid = t >> 5, lane = t & 31;
    const float* p = g_Z + (size_t)bo * MMM;
    for (int i = t; i < MMM / 4; i += 256)
        *(float4*)&zs[i * 4] = *(const float4*)(p + i * 4);
    for (int i = t; i < M * N; i += 256) cis[i] = g_ciT[i];
    __syncthreads();
    int mt = wid & 3;
    int d0 = blockIdx.y * 16 + (wid >> 2) * 8;
    bool act = lane < 25;
    int ml = act ? lane * 4 : 0;
    int m0 = mt * 100 + ml;
    float4 acc[8];
#pragma unroll
    for (int i = 0; i < 8; i++) acc[i] = make_float4(0.f,0.f,0.f,0.f);
#pragma unroll
    for (int kd = 0; kd < M; kd++) {
        float4 v = *(const float4*)&zs[kd * MM + m0];
        float4 c0 = *(const float4*)&cis[kd * N + d0];
        float4 c1 = *(const float4*)&cis[kd * N + d0 + 4];
        acc[0].x += c0.x*v.x; acc[0].y += c0.x*v.y; acc[0].z += c0.x*v.z; acc[0].w += c0.x*v.w;
        acc[1].x += c0.y*v.x; acc[1].y += c0.y*v.y; acc[1].z += c0.y*v.z; acc[1].w += c0.y*v.w;
        acc[2].x += c0.z*v.x; acc[2].y += c0.z*v.y; acc[2].z += c0.z*v.z; acc[2].w += c0.z*v.w;
        acc[3].x += c0.w*v.x; acc[3].y += c0.w*v.y; acc[3].z += c0.w*v.z; acc[3].w += c0.w*v.w;
        acc[4].x += c1.x*v.x; acc[4].y += c1.x*v.y; acc[4].z += c1.x*v.z; acc[4].w += c1.x*v.w;
        acc[5].x += c1.y*v.x; acc[5].y += c1.y*v.y; acc[5].z += c1.y*v.z; acc[5].w += c1.y*v.w;
        acc[6].x += c1.z*v.x; acc[6].y += c1.z*v.y; acc[6].z += c1.z*v.z; acc[6].w += c1.z*v.w;
        acc[7].x += c1.w*v.x; acc[7].y += c1.w*v.y; acc[7].z += c1.w*v.z; acc[7].w += c1.w*v.w;
    }
    if (act) {
        float* q = g_Y2 + (size_t)bo * (N * MM) + m0;
#pragma unroll
        for (int i = 0; i < 8; i++) *(float4*)(q + (size_t)(d0 + i) * MM) = acc[i];
    }
}

// ---------------------------------------------------------------------------
// inv_hw: U1[slice][kh][kw] -> out[slice][h][w], 2 slices per block.
// Stage 1/2 use output-side butterfly: CI(63-n,k) = (-1)^k CI(n,k).
// ---------------------------------------------------------------------------
template<int HB>   // HB = ws*8; warp computes h in [HB,HB+8) and mirrors [56-HB,64-HB)
__device__ __forceinline__ void inv_s1(const float* __restrict__ zcol, float* __restrict__ tcol, bool act) {
    float E[8], Od[8];
#pragma unroll
    for (int i = 0; i < 8; i++) { E[i] = 0.f; Od[i] = 0.f; }
    static_for<20>([&](auto KH) {
        constexpr int kh = KH.value;
        float zv = zcol[kh * 20];
        static_for<8>([&](auto I) {
            constexpr int i = I.value;
            constexpr float c = CI(HB + i, kh);
            if constexpr (kh & 1) Od[i] += zv * c; else E[i] += zv * c;
        });
    });
    if (act) {
#pragma unroll
        for (int i = 0; i < 8; i++) {
            tcol[(HB + i) * 21] = E[i] + Od[i];
            tcol[(63 - HB - i) * 21] = E[i] - Od[i];
        }
    }
}

template<int W0>   // W0 in {0,16}; thread writes w in [W0,W0+16) and [48-W0,64-W0)
__device__ __forceinline__ void inv_s2(const float* __restrict__ trow, float* __restrict__ orow) {
    float E[16], Od[16];
#pragma unroll
    for (int i = 0; i < 16; i++) { E[i] = 0.f; Od[i] = 0.f; }
    static_for<20>([&](auto KW) {
        constexpr int kw = KW.value;
        float tv = trow[kw];
        static_for<16>([&](auto I) {
            constexpr int i = I.value;
            constexpr float c = CI(W0 + i, kw);
            if constexpr (kw & 1) Od[i] += tv * c; else E[i] += tv * c;
        });
    });
#pragma unroll
    for (int j = 0; j < 4; j++) {
        float4 v = make_float4(E[j*4+0] + Od[j*4+0], E[j*4+1] + Od[j*4+1],
                               E[j*4+2] + Od[j*4+2], E[j*4+3] + Od[j*4+3]);
        *(float4*)(orow + W0 + j * 4) = v;
    }
#pragma unroll
    for (int j = 0; j < 4; j++) {
        float4 v = make_float4(E[15-(j*4+0)] - Od[15-(j*4+0)], E[15-(j*4+1)] - Od[15-(j*4+1)],
                               E[15-(j*4+2)] - Od[15-(j*4+2)], E[15-(j*4+3)] - Od[15-(j*4+3)]);
        *(float4*)(orow + (48 - W0) + j * 4) = v;
    }
}

__global__ __launch_bounds__(256) void inv_hw_k(float* __restrict__ out) {
    __shared__ float zs[2][MM];
    __shared__ float tmp[2][64 * 21];
    int t = threadIdx.x, wid = t >> 5, lane = t & 31;
    int sl = wid >> 2, ws = wid & 3;
    int slice = blockIdx.x * 2 + sl;
    int t2 = t & 127;
    const float* p = g_Y2 + (size_t)slice * MM;
    for (int i = t2; i < MM; i += 128) zs[sl][i] = p[i];
    __syncthreads();
    {   // stage 1 (butterfly): tmp[h][kw] from zs[kh][kw]
        bool act = lane < 20;
        int kwc = act ? lane : 0;
        const float* zcol = &zs[sl][kwc];
        float* tcol = &tmp[sl][kwc];
        switch (ws) {
            case 0: inv_s1<0>(zcol, tcol, act); break;
            case 1: inv_s1<8>(zcol, tcol, act); break;
            case 2: inv_s1<16>(zcol, tcol, act); break;
            default: inv_s1<24>(zcol, tcol, act); break;
        }
    }
    __syncthreads();
    {   // stage 2 (butterfly): out[h][w] from tmp[h][kw], direct gmem stores
        int h = (ws & 1) * 32 + lane;
        const float* trow = &tmp[sl][h * 21];
        float* orow = out + (size_t)slice * NN + h * 64;
        if (ws >> 1) inv_s2<16>(trow, orow); else inv_s2<0>(trow, orow);
    }
}

// ---------------------------------------------------------------------------
extern "C" void kernel_launch(void* const* d_in, const int* in_sizes, int n_in,
                              void* d_out, int out_size) {
    const float* x = (const float*)d_in[0];       // (2,32,64,64,64)
    const float* w = (const float*)d_in[1];       // (32,32,20,20,20)
    float* out = (float*)d_out;                   // (2,32,64,64,64)

    init_mats_k<<<5, 256>>>();
    fwd_wh_k<<<B * C * N / 2, 256>>>(x);          // 2048 blocks
    {
        dim3 g(B * C, 4);
        fwd_d_k<<<g, 128>>>();                    // 256 blocks
    }
    {
        dim3 g(63, 4);
        mix_k<<<g, 256>>>(w);                     // 252 blocks
    }
    {
        dim3 g(B * O, 4);
        inv_d_k<<<g, 256>>>();                    // 256 blocks
    }
    inv_hw_k<<<B * O * N / 2, 256>>>(out);        // 2048 blocks
}

// round 6
// speedup vs baseline: 1.2895x; 1.0239x over previous
#include <cuda_runtime.h>

#define B 2
#define C 32
#define O 32
#define N 64
#define M 20
#define MM 400
#define MMM 8000
#define NN 4096

// Scratch (bss, allocation-free)
__device__ float g_Y2[(size_t)B * C * N * MM];   // fwd Y2 [bc][d][m]; reused as U1 [bo][d][m]
__device__ float g_Y3[(size_t)B * C * MMM];      // [bc][kd][m]
__device__ float g_Z [(size_t)B * O * MMM];      // partial sum (c 0..15)
__device__ float g_Z2[(size_t)B * O * MMM];      // partial sum (c 16..31)
__device__ float g_cf [N * M];                   // fwd table  [d][kd]
__device__ float g_ciT[M * N];                   // inv table  [kd][d]

// ---------------------------------------------------------------------------
// Compile-time DCT coefficients (Taylor cos, folded to FFMA immediates)
// ---------------------------------------------------------------------------
__host__ __device__ constexpr double tcos(int a) {      // cos(pi*a/128)
    double x = 3.14159265358979323846264338327950288 * (double)a / 128.0;
    double x2 = x * x, term = 1.0, s = 1.0;
    for (int i = 1; i <= 16; i++) { term *= -x2 / (double)((2 * i - 1) * (2 * i)); s += term; }
    return s;
}
__host__ __device__ constexpr int redu(int k, int n) {
    int a = (k * (2 * n + 1)) % 256;
    return (a > 128) ? 256 - a : a;
}
__host__ __device__ constexpr float CF(int n, int k) {  // forward DCT-II coeff
    double c = tcos(redu(k, n));
    return (k == 0) ? 1.0f : (float)(2.0 * c);
}
__host__ __device__ constexpr float CI(int n, int k) {  // inverse DCT-III coeff
    double c = tcos(redu(k, n));
    return (float)(((k == 0) ? 1.0 : c) / 64.0);
}

template<int I> struct ic { static constexpr int value = I; };
template<int I, int Nn> struct SF {
    template<class F> __device__ __forceinline__ static void run(F&& f) {
        f(ic<I>{}); SF<I + 1, Nn>::run(f);
    }
};
template<int Nn> struct SF<Nn, Nn> {
    template<class F> __device__ __forceinline__ static void run(F&&) {}
};
template<int Nn, class F> __device__ __forceinline__ void static_for(F&& f) { SF<0, Nn>::run(f); }

// ---------------------------------------------------------------------------
__global__ void init_mats_k() {
    int t = blockIdx.x * blockDim.x + threadIdx.x;
    if (t < N * M) {
        int n = t / M, k = t % M;
        g_cf[t] = CF(n, k);
        int k2 = t / N, n2 = t % N;
        g_ciT[t] = CI(n2, k2);
    }
}

// ---------------------------------------------------------------------------
// fwd_wh: x[slice][h][w] -> Y2[slice][kh][kw], 1 slice per 128-thread block.
// Butterfly: CF(63-n,k) = (-1)^k CF(n,k).  Pad 68 -> LDS.128 conflict-free.
// ---------------------------------------------------------------------------
template<int KW0>
__device__ __forceinline__ void fwd_s1(const float* __restrict__ xr, float* __restrict__ tp) {
    float acc[10];
#pragma unroll
    for (int k = 0; k < 10; k++) acc[k] = 0.f;
    static_for<8>([&](auto W4) {
        constexpr int w4 = W4.value;                 // w = 4*w4 .. 4*w4+3
        float4 av = *(const float4*)(xr + w4 * 4);
        float4 bv = *(const float4*)(xr + 60 - w4 * 4);   // holds x[60-4w4 .. 63-4w4]
        // mirror pairs: (w, 63-w)
        float s0 = av.x + bv.w, d0 = av.x - bv.w;
        float s1 = av.y + bv.z, d1 = av.y - bv.z;
        float s2 = av.z + bv.y, d2 = av.z - bv.y;
        float s3 = av.w + bv.x, d3 = av.w - bv.x;
        static_for<10>([&](auto K) {
            constexpr int k = K.value;
            constexpr int kw = KW0 + k;
            constexpr float c0 = CF(w4 * 4 + 0, kw);
            constexpr float c1 = CF(w4 * 4 + 1, kw);
            constexpr float c2 = CF(w4 * 4 + 2, kw);
            constexpr float c3 = CF(w4 * 4 + 3, kw);
            if constexpr (kw & 1) {
                acc[k] += d0 * c0; acc[k] += d1 * c1;
                acc[k] += d2 * c2; acc[k] += d3 * c3;
            } else {
                acc[k] += s0 * c0; acc[k] += s1 * c1;
                acc[k] += s2 * c2; acc[k] += s3 * c3;
            }
        });
    });
#pragma unroll
    for (int k = 0; k < 10; k++) tp[KW0 + k] = acc[k];
}

template<int KH0>
__device__ __forceinline__ void fwd_s2(const float* __restrict__ tcol, float* __restrict__ outp, bool act) {
    float acc[5] = {0.f, 0.f, 0.f, 0.f, 0.f};
    static_for<32>([&](auto H) {
        constexpr int h = H.value;
        float a = tcol[h * 21], b = tcol[(63 - h) * 21];
        float s = a + b, d = a - b;
        static_for<5>([&](auto K) {
            constexpr int k = K.value;
            constexpr int kh = KH0 + k;
            constexpr float c = CF(h, kh);
            acc[k] += ((kh & 1) ? d : s) * c;
        });
    });
    if (act) {
#pragma unroll
        for (int k = 0; k < 5; k++) outp[(KH0 + k) * 20] = acc[k];
    }
}

__global__ __launch_bounds__(128) void fwd_wh_k(const float* __restrict__ x) {
    __shared__ float xs[64 * 68];         // [h][w], pad 68 (16B aligned rows, LDS.128-safe)
    __shared__ float tmp[64 * 21];
    int t = threadIdx.x, wid = t >> 5, lane = t & 31;
    int slice = blockIdx.x;
    const float* xp = x + (size_t)slice * NN;
#pragma unroll
    for (int r = 0; r < 8; r++) {
        int idx = t + r * 128;            // float4 index 0..1023
        int h = idx >> 4, w4 = idx & 15;
        *(float4*)&xs[h * 68 + w4 * 4] = *(const float4*)(xp + idx * 4);
    }
    __syncthreads();
    {   // stage 1: tmp[h][kw] = sum_w xs[h][w]*CF(w,kw)   (butterfly, LDS.128)
        int h = (wid >> 1) * 32 + lane;
        const float* xr = &xs[h * 68];
        float* tp = &tmp[h * 21];
        if (wid & 1) fwd_s1<10>(xr, tp); else fwd_s1<0>(xr, tp);
    }
    __syncthreads();
    {   // stage 2: Y2[kh][kw] = sum_h CF(h,kh)*tmp[h][kw]   (butterfly)
        bool act = lane < 20;
        int kwc = act ? lane : 0;
        const float* tcol = &tmp[kwc];
        float* outp = g_Y2 + (size_t)slice * MM + kwc;
        switch (wid) {
            case 0: fwd_s2<0>(tcol, outp, act); break;
            case 1: fwd_s2<5>(tcol, outp, act); break;
            case 2: fwd_s2<10>(tcol, outp, act); break;
            default: fwd_s2<15>(tcol, outp, act); break;
        }
    }
}

// ---------------------------------------------------------------------------
// fwd_d: Y2[bc][d][m] -> Y3[bc][kd][m]   grid (64 bc, 4 mtile), block 128
// ---------------------------------------------------------------------------
__global__ __launch_bounds__(128) void fwd_d_k() {
    __shared__ float ys2[64 * 100];
    __shared__ float cfs[N * M];
    int bc = blockIdx.x, mt = blockIdx.y;
    int t = threadIdx.x, wid = t >> 5, lane = t & 31;
    const float* src = g_Y2 + (size_t)bc * (N * MM) + mt * 100;
    for (int i = t; i < 1600; i += 128) {
        int d = i / 25, j = (i % 25) * 4;
        *(float4*)&ys2[d * 100 + j] = *(const float4*)(src + (size_t)d * MM + j);
    }
    for (int i = t; i < N * M; i += 128) cfs[i] = g_cf[i];
    __syncthreads();
    int KD0 = wid * 5;
    bool act = lane < 25;
    int ml = act ? lane * 4 : 0;
    float4 acc[5];
#pragma unroll
    for (int k = 0; k < 5; k++) acc[k] = make_float4(0.f, 0.f, 0.f, 0.f);
#pragma unroll 4
    for (int d = 0; d < 64; d++) {
        float4 v = *(const float4*)&ys2[d * 100 + ml];
#pragma unroll
        for (int k = 0; k < 5; k++) {
            float cc = cfs[d * 20 + KD0 + k];
            acc[k].x += cc * v.x; acc[k].y += cc * v.y;
            acc[k].z += cc * v.z; acc[k].w += cc * v.w;
        }
    }
    if (act) {
        float* q = g_Y3 + (size_t)bc * MMM + mt * 100 + lane * 4;
#pragma unroll
        for (int k = 0; k < 5; k++) *(float4*)(q + (size_t)(KD0 + k) * MM) = acc[k];
    }
}

// ---------------------------------------------------------------------------
// mix: partial Z over 16 channels per block.  grid (63 m-tiles, 4 o-tiles, 2 c-halves)
// ---------------------------------------------------------------------------
__global__ __launch_bounds__(256) void mix_k(const float* __restrict__ w) {
    __shared__ float ys[2 * 16 * 128];
    int mbase = blockIdx.x * 128, ot = blockIdx.y, cz = blockIdx.z;
    int c0 = cz * 16;
    int t = threadIdx.x;
    for (int i = t; i < 1024; i += 256) {           // 1024 float4 = 2b*16c*32m4
        int b = i >> 9, c = (i >> 5) & 15, m4 = i & 31;
        int m = mbase + m4 * 4;
        float4 v = make_float4(0.f, 0.f, 0.f, 0.f);
        if (m < MMM) v = *(const float4*)(g_Y3 + (size_t)(b * C + c0 + c) * MMM + m);
        *(float4*)&ys[(size_t)(b * 16 + c) * 128 + m4 * 4] = v;
    }
    __syncthreads();
    int wid = t >> 5, lane = t & 31;
    int o = ot * 8 + wid;
    int m0 = mbase + lane * 4;
    bool valid = m0 < MMM;
    const float* wp = w + ((size_t)c0 * O + o) * MMM + (valid ? m0 : 0);
    float4 a0 = make_float4(0.f,0.f,0.f,0.f), a1 = a0;
#pragma unroll
    for (int cc = 0; cc < 16; cc += 8) {
        float4 wr[8];
#pragma unroll
        for (int j = 0; j < 8; j++)
            wr[j] = *(const float4*)(wp + (size_t)(cc + j) * (O * MMM));
#pragma unroll
        for (int j = 0; j < 8; j++) {
            int c = cc + j;
            float4 y0 = *(const float4*)&ys[c * 128 + lane * 4];
            float4 y1 = *(const float4*)&ys[(16 + c) * 128 + lane * 4];
            a0.x += y0.x*wr[j].x; a0.y += y0.y*wr[j].y; a0.z += y0.z*wr[j].z; a0.w += y0.w*wr[j].w;
            a1.x += y1.x*wr[j].x; a1.y += y1.y*wr[j].y; a1.z += y1.z*wr[j].z; a1.w += y1.w*wr[j].w;
        }
    }
    if (valid) {
        float* Zp = cz ? g_Z2 : g_Z;
        *(float4*)(Zp + (size_t)o * MMM + m0) = a0;
        *(float4*)(Zp + (size_t)(O + o) * MMM + m0) = a1;
    }
}

// ---------------------------------------------------------------------------
// inv_d: (Z+Z2)[bo][kd][m] -> U1[bo][d][m] (into g_Y2)  grid (64 bo, 4 dquarter)
// ---------------------------------------------------------------------------
__global__ __launch_bounds__(256) void inv_d_k() {
    __shared__ float zs[MMM];
    __shared__ float cis[M * N];      // [kd][d]
    int bo = blockIdx.x;
    int t = threadIdx.x, wid = t >> 5, lane = t & 31;
    const float* p = g_Z + (size_t)bo * MMM;
    const float* p2 = g_Z2 + (size_t)bo * MMM;
    for (int i = t; i < MMM / 4; i += 256) {
        float4 a = *(const float4*)(p + i * 4);
        float4 b = *(const float4*)(p2 + i * 4);
        a.x += b.x; a.y += b.y; a.z += b.z; a.w += b.w;
        *(float4*)&zs[i * 4] = a;
    }
    for (int i = t; i < M * N; i += 256) cis[i] = g_ciT[i];
    __syncthreads();
    int mt = wid & 3;
    int d0 = blockIdx.y * 16 + (wid >> 2) * 8;
    bool act = lane < 25;
    int ml = act ? lane * 4 : 0;
    int m0 = mt * 100 + ml;
    float4 acc[8];
#pragma unroll
    for (int i = 0; i < 8; i++) acc[i] = make_float4(0.f,0.f,0.f,0.f);
#pragma unroll
    for (int kd = 0; kd < M; kd++) {
        float4 v = *(const float4*)&zs[kd * MM + m0];
        float4 c0 = *(const float4*)&cis[kd * N + d0];
        float4 c1 = *(const float4*)&cis[kd * N + d0 + 4];
        acc[0].x += c0.x*v.x; acc[0].y += c0.x*v.y; acc[0].z += c0.x*v.z; acc[0].w += c0.x*v.w;
        acc[1].x += c0.y*v.x; acc[1].y += c0.y*v.y; acc[1].z += c0.y*v.z; acc[1].w += c0.y*v.w;
        acc[2].x += c0.z*v.x; acc[2].y += c0.z*v.y; acc[2].z += c0.z*v.z; acc[2].w += c0.z*v.w;
        acc[3].x += c0.w*v.x; acc[3].y += c0.w*v.y; acc[3].z += c0.w*v.z; acc[3].w += c0.w*v.w;
        acc[4].x += c1.x*v.x; acc[4].y += c1.x*v.y; acc[4].z += c1.x*v.z; acc[4].w += c1.x*v.w;
        acc[5].x += c1.y*v.x; acc[5].y += c1.y*v.y; acc[5].z += c1.y*v.z; acc[5].w += c1.y*v.w;
        acc[6].x += c1.z*v.x; acc[6].y += c1.z*v.y; acc[6].z += c1.z*v.z; acc[6].w += c1.z*v.w;
        acc[7].x += c1.w*v.x; acc[7].y += c1.w*v.y; acc[7].z += c1.w*v.z; acc[7].w += c1.w*v.w;
    }
    if (act) {
        float* q = g_Y2 + (size_t)bo * (N * MM) + m0;
#pragma unroll
        for (int i = 0; i < 8; i++) *(float4*)(q + (size_t)(d0 + i) * MM) = acc[i];
    }
}

// ---------------------------------------------------------------------------
// inv_hw: U1[slice][kh][kw] -> out[slice][h][w], 1 slice per 128-thread block.
// Output-side butterfly: CI(63-n,k) = (-1)^k CI(n,k).
// ---------------------------------------------------------------------------
template<int HB>
__device__ __forceinline__ void inv_s1(const float* __restrict__ zcol, float* __restrict__ tcol, bool act) {
    float E[8], Od[8];
#pragma unroll
    for (int i = 0; i < 8; i++) { E[i] = 0.f; Od[i] = 0.f; }
    static_for<20>([&](auto KH) {
        constexpr int kh = KH.value;
        float zv = zcol[kh * 20];
        static_for<8>([&](auto I) {
            constexpr int i = I.value;
            constexpr float c = CI(HB + i, kh);
            if constexpr (kh & 1) Od[i] += zv * c; else E[i] += zv * c;
        });
    });
    if (act) {
#pragma unroll
        for (int i = 0; i < 8; i++) {
            tcol[(HB + i) * 21] = E[i] + Od[i];
            tcol[(63 - HB - i) * 21] = E[i] - Od[i];
        }
    }
}

template<int W0>
__device__ __forceinline__ void inv_s2(const float* __restrict__ trow, float* __restrict__ orow) {
    float E[16], Od[16];
#pragma unroll
    for (int i = 0; i < 16; i++) { E[i] = 0.f; Od[i] = 0.f; }
    static_for<20>([&](auto KW) {
        constexpr int kw = KW.value;
        float tv = trow[kw];
        static_for<16>([&](auto I) {
            constexpr int i = I.value;
            constexpr float c = CI(W0 + i, kw);
            if constexpr (kw & 1) Od[i] += tv * c; else E[i] += tv * c;
        });
    });
#pragma unroll
    for (int j = 0; j < 4; j++) {
        float4 v = make_float4(E[j*4+0] + Od[j*4+0], E[j*4+1] + Od[j*4+1],
                               E[j*4+2] + Od[j*4+2], E[j*4+3] + Od[j*4+3]);
        *(float4*)(orow + W0 + j * 4) = v;
    }
#pragma unroll
    for (int j = 0; j < 4; j++) {
        float4 v = make_float4(E[15-(j*4+0)] - Od[15-(j*4+0)], E[15-(j*4+1)] - Od[15-(j*4+1)],
                               E[15-(j*4+2)] - Od[15-(j*4+2)], E[15-(j*4+3)] - Od[15-(j*4+3)]);
        *(float4*)(orow + (48 - W0) + j * 4) = v;
    }
}

__global__ __launch_bounds__(128) void inv_hw_k(float* __restrict__ out) {
    __shared__ float zs[MM];
    __shared__ float tmp[64 * 21];
    int t = threadIdx.x, wid = t >> 5, lane = t & 31;
    int slice = blockIdx.x;
    const float* p = g_Y2 + (size_t)slice * MM;
    for (int i = t; i < MM; i += 128) zs[i] = p[i];
    __syncthreads();
    {   // stage 1 (butterfly): tmp[h][kw] from zs[kh][kw]
        bool act = lane < 20;
        int kwc = act ? lane : 0;
        const float* zcol = &zs[kwc];
        float* tcol = &tmp[kwc];
        switch (wid) {
            case 0: inv_s1<0>(zcol, tcol, act); break;
            case 1: inv_s1<8>(zcol, tcol, act); break;
            case 2: inv_s1<16>(zcol, tcol, act); break;
            default: inv_s1<24>(zcol, tcol, act); break;
        }
    }
    __syncthreads();
    {   // stage 2 (butterfly): out[h][w] from tmp[h][kw], direct gmem stores
        int h = (wid & 1) * 32 + lane;
        const float* trow = &tmp[h * 21];
        float* orow = out + (size_t)slice * NN + h * 64;
        if (wid >> 1) inv_s2<16>(trow, orow); else inv_s2<0>(trow, orow);
    }
}

// ---------------------------------------------------------------------------
extern "C" void kernel_launch(void* const* d_in, const int* in_sizes, int n_in,
                              void* d_out, int out_size) {
    const float* x = (const float*)d_in[0];       // (2,32,64,64,64)
    const float* w = (const float*)d_in[1];       // (32,32,20,20,20)
    float* out = (float*)d_out;                   // (2,32,64,64,64)

    init_mats_k<<<5, 256>>>();
    fwd_wh_k<<<B * C * N, 128>>>(x);              // 4096 blocks
    {
        dim3 g(B * C, 4);
        fwd_d_k<<<g, 128>>>();                    // 256 blocks
    }
    {
        dim3 g(63, 4, 2);
        mix_k<<<g, 256>>>(w);                     // 504 blocks
    }
    {
        dim3 g(B * O, 4);
        inv_d_k<<<g, 256>>>();                    // 256 blocks
    }
    inv_hw_k<<<B * O * N, 128>>>(out);            // 4096 blocks
}